// round 13
// baseline (speedup 1.0000x reference)
#include <cuda_runtime.h>
#include <cuda_fp16.h>

// Problem constants (fixed by the reference).
#define Bv 2
#define Cv 48
#define CP 24              // channel pairs
#define Hv 80
#define Wv 128
#define MDv 4
#define RANGEv 81          // (2*MD+1)^2
#define HWv (Hv * Wv)      // 10240
#define CHWv (Cv * HWv)    // 491520

// Channel-pair quad-packed normalized features (fp16).
// Entry (b, c2, y, x) is 16 bytes:
//   .x = half2( v[c0][y ][x], v[c0][y ][x1] )
//   .y = half2( v[c0][y1][x], v[c0][y1][x1] )
//   .z = half2( v[c1][y ][x], v[c1][y ][x1] )
//   .w = half2( v[c1][y1][x], v[c1][y1][x1] )
// with c0=2*c2, c1=c0+1, x1=min(x+1,W-1), y1=min(y+1,H-1).
__device__ uint4 g_p1[Bv * CP * HWv];   // normalized feature1 (backward source)
__device__ uint4 g_p2[Bv * CP * HWv];   // normalized feature2 (forward source)

// ---------------------------------------------------------------------------
// Fused prep kernel: one block per (b, y) row.
// ---------------------------------------------------------------------------
__global__ __launch_bounds__(256)
void prep_kernel(const float* __restrict__ f1,
                 const float* __restrict__ f2) {
    const int by = blockIdx.x;          // b*Hv + y
    const int b = by / Hv;
    const int y = by - b * Hv;
    const int y1 = min(y + 1, Hv - 1);
    const int tid = threadIdx.x;

    __shared__ float srn1[2][Wv];
    __shared__ float srn2[2][Wv];

    {
        const int row = tid >> 7;       // 0 or 1
        const int x = tid & 127;
        const int yy = row ? y1 : y;
        const float* s1 = f1 + b * CHWv + yy * Wv + x;
        const float* s2 = f2 + b * CHWv + yy * Wv + x;
        float a = 0.f, c = 0.f;
#pragma unroll
        for (int ch = 0; ch < Cv; ch++) {
            float v1 = s1[ch * HWv];
            float v2 = s2[ch * HWv];
            a = fmaf(v1, v1, a);
            c = fmaf(v2, v2, c);
        }
        srn1[row][x] = rsqrtf(a + 1e-6f);
        srn2[row][x] = rsqrtf(c + 1e-6f);
    }
    __syncthreads();

#pragma unroll
    for (int it = 0; it < 12; it++) {
        const int item = it * 256 + tid;    // 0..3071
        const int x = item & 127;
        const int c2 = item >> 7;           // 0..23
        const int x1 = min(x + 1, Wv - 1);
        const int c0 = 2 * c2;

        const float rnA00 = srn1[0][x];
        const float rnA01 = srn1[0][x1];
        const float rnA10 = srn1[1][x];
        const float rnA11 = srn1[1][x1];
        const float rnB00 = srn2[0][x];
        const float rnB01 = srn2[0][x1];
        const float rnB10 = srn2[1][x];
        const float rnB11 = srn2[1][x1];

        uint4 q1, q2;
#pragma unroll
        for (int k = 0; k < 2; k++) {
            const int cb = (b * Cv + c0 + k) * HWv;
            float a00 = f1[cb + y * Wv + x]    * rnA00;
            float a01 = f1[cb + y * Wv + x1]   * rnA01;
            float a10 = f1[cb + y1 * Wv + x]   * rnA10;
            float a11 = f1[cb + y1 * Wv + x1]  * rnA11;
            float b00 = f2[cb + y * Wv + x]    * rnB00;
            float b01 = f2[cb + y * Wv + x1]   * rnB01;
            float b10 = f2[cb + y1 * Wv + x]   * rnB10;
            float b11 = f2[cb + y1 * Wv + x1]  * rnB11;

            unsigned* q1p = k == 0 ? &q1.x : &q1.z;
            unsigned* q2p = k == 0 ? &q2.x : &q2.z;
            *reinterpret_cast<half2*>(q1p)     = __floats2half2_rn(a00, a01);
            *reinterpret_cast<half2*>(q1p + 1) = __floats2half2_rn(a10, a11);
            *reinterpret_cast<half2*>(q2p)     = __floats2half2_rn(b00, b01);
            *reinterpret_cast<half2*>(q2p + 1) = __floats2half2_rn(b10, b11);
        }
        const int n = ((b * CP + c2) * Hv + y) * Wv + x;
        g_p1[n] = q1;
        g_p2[n] = q2;
    }
}

// ---------------------------------------------------------------------------
// Per-axis sampling, replicating the reference arithmetic order exactly:
//   g = 2*v/(D-1) - 1 ; ix = ((g+1)*D - 1) * 0.5
// ---------------------------------------------------------------------------
__device__ __forceinline__ void axis_sample(float v, int D,
                                            int& i0, float& wf, float& mv) {
    float g = (2.0f * v) / (float)(D - 1) - 1.0f;
    float ix = ((g + 1.0f) * (float)D - 1.0f) * 0.5f;

    float ixb = fminf(fmaxf(ix, 0.0f), (float)(D - 1));
    float x0f = floorf(ixb);
    wf = ixb - x0f;
    i0 = (int)x0f;

    float fx = floorf(ix);
    float mw = ix - fx;
    float in0 = (fx >= 0.0f && fx <= (float)(D - 1)) ? 1.0f : 0.0f;
    float in1 = (fx + 1.0f >= 0.0f && fx + 1.0f <= (float)(D - 1)) ? 1.0f : 0.0f;
    mv = (1.0f - mw) * in0 + mw * in1;
}

// Accumulate one channel from two half2-pairs (one quad each), fp32 math.
__device__ __forceinline__ void quad_acc2(unsigned fx_, unsigned fy_,
                                          unsigned bx_, unsigned by_,
                                          float f00, float f01, float f10, float f11,
                                          float g00, float g01, float g10, float g11,
                                          float& acc) {
    const float2 ft = __half22float2(*reinterpret_cast<const half2*>(&fx_));
    const float2 fb = __half22float2(*reinterpret_cast<const half2*>(&fy_));
    const float2 bt = __half22float2(*reinterpret_cast<const half2*>(&bx_));
    const float2 bb = __half22float2(*reinterpret_cast<const half2*>(&by_));
    float fw = f00 * ft.x;
    fw = fmaf(f01, ft.y, fw);
    fw = fmaf(f10, fb.x, fw);
    fw = fmaf(f11, fb.y, fw);
    float bw = g00 * bt.x;
    bw = fmaf(g01, bt.y, bw);
    bw = fmaf(g10, bb.x, bw);
    bw = fmaf(g11, bb.y, bw);
    acc = fmaf(fw, bw, acc);
}

// ---------------------------------------------------------------------------
// Kernel 2: cost volume. Block (9 du, 32 w): threadIdx.x = du (fast within
// warp), threadIdx.y = w; dv fixed per block (gridDim.z = B * 9 dv).
// fp32 lerp math (rel_err 2.94e-4). Channel unroll 3 -> 6 LDG.128 in flight
// per warp to keep the L1 queue fed (L1 was 85% busy at unroll 2).
// t = 0.5 => forward disp = +d (samples f2), backward = -d (samples f1).
// ---------------------------------------------------------------------------
__global__ __launch_bounds__(288, 5)
void costvol_kernel(const float* __restrict__ BM, float* __restrict__ out) {
    const int dui = threadIdx.x;           // 0..8  (du fast within warp)
    const int w = (blockIdx.x << 5) + threadIdx.y;
    const int h = blockIdx.y;
    const int b = blockIdx.z / 9;
    const int dvi = blockIdx.z - b * 9;    // 0..8  (dv fixed per block)

    const float bmx = BM[((b * 2 + 0) * Hv + h) * Wv + w];
    const float bmy = BM[((b * 2 + 1) * Hv + h) * Wv + w];
    const float dytot = bmy + (float)(dvi - MDv);
    const float dxtot = bmx + (float)(dui - MDv);

    int y0f, y0b, x0f, x0b;
    float wyf, wyb, mvyf, mvyb, wxf, wxb, mvxf, mvxb;
    axis_sample((float)h + dytot, Hv, y0f, wyf, mvyf);
    axis_sample((float)h - dytot, Hv, y0b, wyb, mvyb);
    axis_sample((float)w + dxtot, Wv, x0f, wxf, mvxf);
    axis_sample((float)w - dxtot, Wv, x0b, wxb, mvxb);

    float acc0 = 0.0f, acc1 = 0.0f;
    if ((mvxf * mvyf >= 0.999f) && (mvxb * mvyb >= 0.999f)) {
        const float omwyf = 1.0f - wyf;
        const float omwyb = 1.0f - wyb;
        const float f00 = (1.0f - wxf) * omwyf;
        const float f01 = wxf * omwyf;
        const float f10 = (1.0f - wxf) * wyf;
        const float f11 = wxf * wyf;
        const float g00 = (1.0f - wxb) * omwyb;
        const float g01 = wxb * omwyb;
        const float g10 = (1.0f - wxb) * wyb;
        const float g11 = wxb * wyb;

        const uint4* __restrict__ qf = g_p2 + b * CP * HWv + y0f * Wv + x0f;
        const uint4* __restrict__ qb = g_p1 + b * CP * HWv + y0b * Wv + x0b;

#pragma unroll 3
        for (int c2 = 0; c2 < CP; c2++) {
            const uint4 uf = qf[c2 * HWv];
            const uint4 ub = qb[c2 * HWv];
            quad_acc2(uf.x, uf.y, ub.x, ub.y,
                      f00, f01, f10, f11, g00, g01, g10, g11, acc0);
            quad_acc2(uf.z, uf.w, ub.z, ub.w,
                      f00, f01, f10, f11, g00, g01, g10, g11, acc1);
        }
    }
    out[((b * RANGEv + dvi * 9 + dui) * Hv + h) * Wv + w] = acc0 + acc1;
}

// ---------------------------------------------------------------------------
extern "C" void kernel_launch(void* const* d_in, const int* in_sizes, int n_in,
                              void* d_out, int out_size) {
    int bm_idx = 2;
    for (int i = 0; i < n_in; i++)
        if (in_sizes[i] == Bv * 2 * Hv * Wv) bm_idx = i;
    int fidx[2], k = 0;
    for (int i = 0; i < n_in && k < 2; i++)
        if (i != bm_idx) fidx[k++] = i;

    const float* f1 = (const float*)d_in[fidx[0]];
    const float* f2 = (const float*)d_in[fidx[1]];
    const float* BM = (const float*)d_in[bm_idx];
    float* out = (float*)d_out;

    prep_kernel<<<Bv * Hv, 256>>>(f1, f2);

    dim3 grid(Wv / 32, Hv, Bv * 9);
    dim3 blk(9, 32);
    costvol_kernel<<<grid, blk>>>(BM, out);
}

// round 14
// speedup vs baseline: 1.0035x; 1.0035x over previous
#include <cuda_runtime.h>
#include <cuda_fp16.h>

// Problem constants (fixed by the reference).
#define Bv 2
#define Cv 48
#define CP 24              // channel pairs
#define Hv 80
#define Wv 128
#define MDv 4
#define RANGEv 81          // (2*MD+1)^2
#define HWv (Hv * Wv)      // 10240
#define CHWv (Cv * HWv)    // 491520

// Channel-pair quad-packed normalized features (fp16).
// Entry (b, c2, y, x) is 16 bytes:
//   .x = half2( v[c0][y ][x], v[c0][y ][x1] )
//   .y = half2( v[c0][y1][x], v[c0][y1][x1] )
//   .z = half2( v[c1][y ][x], v[c1][y ][x1] )
//   .w = half2( v[c1][y1][x], v[c1][y1][x1] )
// with c0=2*c2, c1=c0+1, x1=min(x+1,W-1), y1=min(y+1,H-1).
__device__ uint4 g_p1[Bv * CP * HWv];   // normalized feature1 (backward source)
__device__ uint4 g_p2[Bv * CP * HWv];   // normalized feature2 (forward source)

// ---------------------------------------------------------------------------
// Fused prep kernel: one block per (b, y) row.
// ---------------------------------------------------------------------------
__global__ __launch_bounds__(256)
void prep_kernel(const float* __restrict__ f1,
                 const float* __restrict__ f2) {
    const int by = blockIdx.x;          // b*Hv + y
    const int b = by / Hv;
    const int y = by - b * Hv;
    const int y1 = min(y + 1, Hv - 1);
    const int tid = threadIdx.x;

    __shared__ float srn1[2][Wv];
    __shared__ float srn2[2][Wv];

    {
        const int row = tid >> 7;       // 0 or 1
        const int x = tid & 127;
        const int yy = row ? y1 : y;
        const float* s1 = f1 + b * CHWv + yy * Wv + x;
        const float* s2 = f2 + b * CHWv + yy * Wv + x;
        float a = 0.f, c = 0.f;
#pragma unroll
        for (int ch = 0; ch < Cv; ch++) {
            float v1 = s1[ch * HWv];
            float v2 = s2[ch * HWv];
            a = fmaf(v1, v1, a);
            c = fmaf(v2, v2, c);
        }
        srn1[row][x] = rsqrtf(a + 1e-6f);
        srn2[row][x] = rsqrtf(c + 1e-6f);
    }
    __syncthreads();

#pragma unroll
    for (int it = 0; it < 12; it++) {
        const int item = it * 256 + tid;    // 0..3071
        const int x = item & 127;
        const int c2 = item >> 7;           // 0..23
        const int x1 = min(x + 1, Wv - 1);
        const int c0 = 2 * c2;

        const float rnA00 = srn1[0][x];
        const float rnA01 = srn1[0][x1];
        const float rnA10 = srn1[1][x];
        const float rnA11 = srn1[1][x1];
        const float rnB00 = srn2[0][x];
        const float rnB01 = srn2[0][x1];
        const float rnB10 = srn2[1][x];
        const float rnB11 = srn2[1][x1];

        uint4 q1, q2;
#pragma unroll
        for (int k = 0; k < 2; k++) {
            const int cb = (b * Cv + c0 + k) * HWv;
            float a00 = f1[cb + y * Wv + x]    * rnA00;
            float a01 = f1[cb + y * Wv + x1]   * rnA01;
            float a10 = f1[cb + y1 * Wv + x]   * rnA10;
            float a11 = f1[cb + y1 * Wv + x1]  * rnA11;
            float b00 = f2[cb + y * Wv + x]    * rnB00;
            float b01 = f2[cb + y * Wv + x1]   * rnB01;
            float b10 = f2[cb + y1 * Wv + x]   * rnB10;
            float b11 = f2[cb + y1 * Wv + x1]  * rnB11;

            unsigned* q1p = k == 0 ? &q1.x : &q1.z;
            unsigned* q2p = k == 0 ? &q2.x : &q2.z;
            *reinterpret_cast<half2*>(q1p)     = __floats2half2_rn(a00, a01);
            *reinterpret_cast<half2*>(q1p + 1) = __floats2half2_rn(a10, a11);
            *reinterpret_cast<half2*>(q2p)     = __floats2half2_rn(b00, b01);
            *reinterpret_cast<half2*>(q2p + 1) = __floats2half2_rn(b10, b11);
        }
        const int n = ((b * CP + c2) * Hv + y) * Wv + x;
        g_p1[n] = q1;
        g_p2[n] = q2;
    }
}

// ---------------------------------------------------------------------------
// Per-axis sampling, replicating the reference arithmetic order exactly:
//   g = 2*v/(D-1) - 1 ; ix = ((g+1)*D - 1) * 0.5
// ---------------------------------------------------------------------------
__device__ __forceinline__ void axis_sample(float v, int D,
                                            int& i0, float& wf, float& mv) {
    float g = (2.0f * v) / (float)(D - 1) - 1.0f;
    float ix = ((g + 1.0f) * (float)D - 1.0f) * 0.5f;

    float ixb = fminf(fmaxf(ix, 0.0f), (float)(D - 1));
    float x0f = floorf(ixb);
    wf = ixb - x0f;
    i0 = (int)x0f;

    float fx = floorf(ix);
    float mw = ix - fx;
    float in0 = (fx >= 0.0f && fx <= (float)(D - 1)) ? 1.0f : 0.0f;
    float in1 = (fx + 1.0f >= 0.0f && fx + 1.0f <= (float)(D - 1)) ? 1.0f : 0.0f;
    mv = (1.0f - mw) * in0 + mw * in1;
}

// Accumulate one channel from two half2-pairs (one quad each), fp32 math.
__device__ __forceinline__ void quad_acc2(unsigned fx_, unsigned fy_,
                                          unsigned bx_, unsigned by_,
                                          float f00, float f01, float f10, float f11,
                                          float g00, float g01, float g10, float g11,
                                          float& acc) {
    const float2 ft = __half22float2(*reinterpret_cast<const half2*>(&fx_));
    const float2 fb = __half22float2(*reinterpret_cast<const half2*>(&fy_));
    const float2 bt = __half22float2(*reinterpret_cast<const half2*>(&bx_));
    const float2 bb = __half22float2(*reinterpret_cast<const half2*>(&by_));
    float fw = f00 * ft.x;
    fw = fmaf(f01, ft.y, fw);
    fw = fmaf(f10, fb.x, fw);
    fw = fmaf(f11, fb.y, fw);
    float bw = g00 * bt.x;
    bw = fmaf(g01, bt.y, bw);
    bw = fmaf(g10, bb.x, bw);
    bw = fmaf(g11, bb.y, bw);
    acc = fmaf(fw, bw, acc);
}

// ---------------------------------------------------------------------------
// Kernel 2: cost volume. Block (9 du, 32 w): threadIdx.x = du (fast within
// warp), threadIdx.y = w; dv fixed per block (gridDim.z = B * 9 dv).
// fp32 lerp math (rel_err 2.94e-4). min-blocks 6 (regs<=37) to lift resident
// warps 45 -> 54 and close the issue gap to the L1 wavefront floor.
// t = 0.5 => forward disp = +d (samples f2), backward = -d (samples f1).
// ---------------------------------------------------------------------------
__global__ __launch_bounds__(288, 6)
void costvol_kernel(const float* __restrict__ BM, float* __restrict__ out) {
    const int dui = threadIdx.x;           // 0..8  (du fast within warp)
    const int w = (blockIdx.x << 5) + threadIdx.y;
    const int h = blockIdx.y;
    const int b = blockIdx.z / 9;
    const int dvi = blockIdx.z - b * 9;    // 0..8  (dv fixed per block)

    const float bmx = BM[((b * 2 + 0) * Hv + h) * Wv + w];
    const float bmy = BM[((b * 2 + 1) * Hv + h) * Wv + w];
    const float dytot = bmy + (float)(dvi - MDv);
    const float dxtot = bmx + (float)(dui - MDv);

    int y0f, y0b, x0f, x0b;
    float wyf, wyb, mvyf, mvyb, wxf, wxb, mvxf, mvxb;
    axis_sample((float)h + dytot, Hv, y0f, wyf, mvyf);
    axis_sample((float)h - dytot, Hv, y0b, wyb, mvyb);
    axis_sample((float)w + dxtot, Wv, x0f, wxf, mvxf);
    axis_sample((float)w - dxtot, Wv, x0b, wxb, mvxb);

    float acc0 = 0.0f, acc1 = 0.0f;
    if ((mvxf * mvyf >= 0.999f) && (mvxb * mvyb >= 0.999f)) {
        const float omwyf = 1.0f - wyf;
        const float omwyb = 1.0f - wyb;
        const float f00 = (1.0f - wxf) * omwyf;
        const float f01 = wxf * omwyf;
        const float f10 = (1.0f - wxf) * wyf;
        const float f11 = wxf * wyf;
        const float g00 = (1.0f - wxb) * omwyb;
        const float g01 = wxb * omwyb;
        const float g10 = (1.0f - wxb) * wyb;
        const float g11 = wxb * wyb;

        const uint4* __restrict__ qf = g_p2 + b * CP * HWv + y0f * Wv + x0f;
        const uint4* __restrict__ qb = g_p1 + b * CP * HWv + y0b * Wv + x0b;

#pragma unroll 2
        for (int c2 = 0; c2 < CP; c2++) {
            const uint4 uf = qf[c2 * HWv];
            const uint4 ub = qb[c2 * HWv];
            quad_acc2(uf.x, uf.y, ub.x, ub.y,
                      f00, f01, f10, f11, g00, g01, g10, g11, acc0);
            quad_acc2(uf.z, uf.w, ub.z, ub.w,
                      f00, f01, f10, f11, g00, g01, g10, g11, acc1);
        }
    }
    out[((b * RANGEv + dvi * 9 + dui) * Hv + h) * Wv + w] = acc0 + acc1;
}

// ---------------------------------------------------------------------------
extern "C" void kernel_launch(void* const* d_in, const int* in_sizes, int n_in,
                              void* d_out, int out_size) {
    int bm_idx = 2;
    for (int i = 0; i < n_in; i++)
        if (in_sizes[i] == Bv * 2 * Hv * Wv) bm_idx = i;
    int fidx[2], k = 0;
    for (int i = 0; i < n_in && k < 2; i++)
        if (i != bm_idx) fidx[k++] = i;

    const float* f1 = (const float*)d_in[fidx[0]];
    const float* f2 = (const float*)d_in[fidx[1]];
    const float* BM = (const float*)d_in[bm_idx];
    float* out = (float*)d_out;

    prep_kernel<<<Bv * Hv, 256>>>(f1, f2);

    dim3 grid(Wv / 32, Hv, Bv * 9);
    dim3 blk(9, 32);
    costvol_kernel<<<grid, blk>>>(BM, out);
}

// round 15
// speedup vs baseline: 1.0260x; 1.0224x over previous
#include <cuda_runtime.h>
#include <cuda_fp16.h>

// Problem constants (fixed by the reference).
#define Bv 2
#define Cv 48
#define CP 24              // channel pairs
#define Hv 80
#define Wv 128
#define MDv 4
#define RANGEv 81          // (2*MD+1)^2
#define HWv (Hv * Wv)      // 10240
#define CHWv (Cv * HWv)    // 491520

// Channel-pair quad-packed normalized features (fp16).
// Entry (b, c2, y, x) is 16 bytes:
//   .x = half2( v[c0][y ][x], v[c0][y ][x1] )
//   .y = half2( v[c0][y1][x], v[c0][y1][x1] )
//   .z = half2( v[c1][y ][x], v[c1][y ][x1] )
//   .w = half2( v[c1][y1][x], v[c1][y1][x1] )
// with c0=2*c2, c1=c0+1, x1=min(x+1,W-1), y1=min(y+1,H-1).
__device__ uint4 g_p1[Bv * CP * HWv];   // normalized feature1 (backward source)
__device__ uint4 g_p2[Bv * CP * HWv];   // normalized feature2 (forward source)

// ---------------------------------------------------------------------------
// Fused prep kernel: one block per (b, y) row.
// ---------------------------------------------------------------------------
__global__ __launch_bounds__(256)
void prep_kernel(const float* __restrict__ f1,
                 const float* __restrict__ f2) {
    const int by = blockIdx.x;          // b*Hv + y
    const int b = by / Hv;
    const int y = by - b * Hv;
    const int y1 = min(y + 1, Hv - 1);
    const int tid = threadIdx.x;

    __shared__ float srn1[2][Wv];
    __shared__ float srn2[2][Wv];

    {
        const int row = tid >> 7;       // 0 or 1
        const int x = tid & 127;
        const int yy = row ? y1 : y;
        const float* s1 = f1 + b * CHWv + yy * Wv + x;
        const float* s2 = f2 + b * CHWv + yy * Wv + x;
        float a = 0.f, c = 0.f;
#pragma unroll
        for (int ch = 0; ch < Cv; ch++) {
            float v1 = s1[ch * HWv];
            float v2 = s2[ch * HWv];
            a = fmaf(v1, v1, a);
            c = fmaf(v2, v2, c);
        }
        srn1[row][x] = rsqrtf(a + 1e-6f);
        srn2[row][x] = rsqrtf(c + 1e-6f);
    }
    __syncthreads();

#pragma unroll
    for (int it = 0; it < 12; it++) {
        const int item = it * 256 + tid;    // 0..3071
        const int x = item & 127;
        const int c2 = item >> 7;           // 0..23
        const int x1 = min(x + 1, Wv - 1);
        const int c0 = 2 * c2;

        const float rnA00 = srn1[0][x];
        const float rnA01 = srn1[0][x1];
        const float rnA10 = srn1[1][x];
        const float rnA11 = srn1[1][x1];
        const float rnB00 = srn2[0][x];
        const float rnB01 = srn2[0][x1];
        const float rnB10 = srn2[1][x];
        const float rnB11 = srn2[1][x1];

        uint4 q1, q2;
#pragma unroll
        for (int k = 0; k < 2; k++) {
            const int cb = (b * Cv + c0 + k) * HWv;
            float a00 = f1[cb + y * Wv + x]    * rnA00;
            float a01 = f1[cb + y * Wv + x1]   * rnA01;
            float a10 = f1[cb + y1 * Wv + x]   * rnA10;
            float a11 = f1[cb + y1 * Wv + x1]  * rnA11;
            float b00 = f2[cb + y * Wv + x]    * rnB00;
            float b01 = f2[cb + y * Wv + x1]   * rnB01;
            float b10 = f2[cb + y1 * Wv + x]   * rnB10;
            float b11 = f2[cb + y1 * Wv + x1]  * rnB11;

            unsigned* q1p = k == 0 ? &q1.x : &q1.z;
            unsigned* q2p = k == 0 ? &q2.x : &q2.z;
            *reinterpret_cast<half2*>(q1p)     = __floats2half2_rn(a00, a01);
            *reinterpret_cast<half2*>(q1p + 1) = __floats2half2_rn(a10, a11);
            *reinterpret_cast<half2*>(q2p)     = __floats2half2_rn(b00, b01);
            *reinterpret_cast<half2*>(q2p + 1) = __floats2half2_rn(b10, b11);
        }
        const int n = ((b * CP + c2) * Hv + y) * Wv + x;
        g_p1[n] = q1;
        g_p2[n] = q2;
    }
}

// ---------------------------------------------------------------------------
// Per-axis sampling, replicating the reference arithmetic order exactly:
//   g = 2*v/(D-1) - 1 ; ix = ((g+1)*D - 1) * 0.5
// ---------------------------------------------------------------------------
__device__ __forceinline__ void axis_sample(float v, int D,
                                            int& i0, float& wf, float& mv) {
    float g = (2.0f * v) / (float)(D - 1) - 1.0f;
    float ix = ((g + 1.0f) * (float)D - 1.0f) * 0.5f;

    float ixb = fminf(fmaxf(ix, 0.0f), (float)(D - 1));
    float x0f = floorf(ixb);
    wf = ixb - x0f;
    i0 = (int)x0f;

    float fx = floorf(ix);
    float mw = ix - fx;
    float in0 = (fx >= 0.0f && fx <= (float)(D - 1)) ? 1.0f : 0.0f;
    float in1 = (fx + 1.0f >= 0.0f && fx + 1.0f <= (float)(D - 1)) ? 1.0f : 0.0f;
    mv = (1.0f - mw) * in0 + mw * in1;
}

// ---------------------------------------------------------------------------
// Kernel 2: cost volume. Block (9 du, 32 w): threadIdx.x = du (fast within
// warp), threadIdx.y = w; dv fixed per block (gridDim.z = B * 9 dv).
// Inner loop: half2 y-lerp (R12 body, best measured). Output staged through
// padded smem and stored coalesced (1 line/warp vs ~9 scattered before).
// t = 0.5 => forward disp = +d (samples f2), backward = -d (samples f1).
// ---------------------------------------------------------------------------
__global__ __launch_bounds__(288, 6)
void costvol_kernel(const float* __restrict__ BM, float* __restrict__ out) {
    const int dui = threadIdx.x;           // 0..8  (du fast within warp)
    const int wl = threadIdx.y;            // 0..31 local w
    const int w = (blockIdx.x << 5) + wl;
    const int h = blockIdx.y;
    const int b = blockIdx.z / 9;
    const int dvi = blockIdx.z - b * 9;    // 0..8  (dv fixed per block)

    __shared__ float sacc[9 * 33];         // padded: bank = (dui + wl) % 32

    const float bmx = BM[((b * 2 + 0) * Hv + h) * Wv + w];
    const float bmy = BM[((b * 2 + 1) * Hv + h) * Wv + w];
    const float dytot = bmy + (float)(dvi - MDv);
    const float dxtot = bmx + (float)(dui - MDv);

    int y0f, y0b, x0f, x0b;
    float wyf, wyb, mvyf, mvyb, wxf, wxb, mvxf, mvxb;
    axis_sample((float)h + dytot, Hv, y0f, wyf, mvyf);
    axis_sample((float)h - dytot, Hv, y0b, wyb, mvyb);
    axis_sample((float)w + dxtot, Wv, x0f, wxf, mvxf);
    axis_sample((float)w - dxtot, Wv, x0b, wxb, mvxb);

    float acc0 = 0.0f, acc1 = 0.0f;
    if ((mvxf * mvyf >= 0.999f) && (mvxb * mvyb >= 0.999f)) {
        const half2 wy2f   = __float2half2_rn(wyf);
        const half2 omwy2f = __float2half2_rn(1.0f - wyf);
        const half2 wy2b   = __float2half2_rn(wyb);
        const half2 omwy2b = __float2half2_rn(1.0f - wyb);
        const float omwxf = 1.0f - wxf;
        const float omwxb = 1.0f - wxb;

        const uint4* __restrict__ qf = g_p2 + b * CP * HWv + y0f * Wv + x0f;
        const uint4* __restrict__ qb = g_p1 + b * CP * HWv + y0b * Wv + x0b;

#pragma unroll 2
        for (int c2 = 0; c2 < CP; c2++) {
            const uint4 uf = qf[c2 * HWv];
            const uint4 ub = qb[c2 * HWv];

            {
                const half2 vf = __hfma2(*reinterpret_cast<const half2*>(&uf.x), omwy2f,
                                         __hmul2(*reinterpret_cast<const half2*>(&uf.y), wy2f));
                const half2 vb = __hfma2(*reinterpret_cast<const half2*>(&ub.x), omwy2b,
                                         __hmul2(*reinterpret_cast<const half2*>(&ub.y), wy2b));
                const float2 fv = __half22float2(vf);
                const float2 bv = __half22float2(vb);
                const float fw = fmaf(wxf, fv.y, fv.x * omwxf);
                const float bw = fmaf(wxb, bv.y, bv.x * omwxb);
                acc0 = fmaf(fw, bw, acc0);
            }
            {
                const half2 vf = __hfma2(*reinterpret_cast<const half2*>(&uf.z), omwy2f,
                                         __hmul2(*reinterpret_cast<const half2*>(&uf.w), wy2f));
                const half2 vb = __hfma2(*reinterpret_cast<const half2*>(&ub.z), omwy2b,
                                         __hmul2(*reinterpret_cast<const half2*>(&ub.w), wy2b));
                const float2 fv = __half22float2(vf);
                const float2 bv = __half22float2(vb);
                const float fw = fmaf(wxf, fv.y, fv.x * omwxf);
                const float bw = fmaf(wxb, bv.y, bv.x * omwxb);
                acc1 = fmaf(fw, bw, acc1);
            }
        }
    }

    // Stage result; write coalesced (warp = one du-plane, 32 consecutive w).
    sacc[dui * 33 + wl] = acc0 + acc1;
    __syncthreads();
    const int lin = dui + 9 * wl;          // 0..287 (block-linear tid)
    const int p = lin >> 5;                // du-plane 0..8
    const int wi = lin & 31;               // w within tile
    out[((b * RANGEv + dvi * 9 + p) * Hv + h) * Wv + (blockIdx.x << 5) + wi] =
        sacc[p * 33 + wi];
}

// ---------------------------------------------------------------------------
extern "C" void kernel_launch(void* const* d_in, const int* in_sizes, int n_in,
                              void* d_out, int out_size) {
    int bm_idx = 2;
    for (int i = 0; i < n_in; i++)
        if (in_sizes[i] == Bv * 2 * Hv * Wv) bm_idx = i;
    int fidx[2], k = 0;
    for (int i = 0; i < n_in && k < 2; i++)
        if (i != bm_idx) fidx[k++] = i;

    const float* f1 = (const float*)d_in[fidx[0]];
    const float* f2 = (const float*)d_in[fidx[1]];
    const float* BM = (const float*)d_in[bm_idx];
    float* out = (float*)d_out;

    prep_kernel<<<Bv * Hv, 256>>>(f1, f2);

    dim3 grid(Wv / 32, Hv, Bv * 9);
    dim3 blk(9, 32);
    costvol_kernel<<<grid, blk>>>(BM, out);
}